// round 15
// baseline (speedup 1.0000x reference)
#include <cuda_runtime.h>
#include <cuda_bf16.h>
#include <cstdint>

#define N_TOTAL 8388608   // 2^23

__device__ float2 g_scratch[N_TOTAL];   // transposed intermediate

__host__ __device__ __forceinline__ constexpr int brev_c(int x, int K) {
    int r = 0;
    for (int b = 0; b < K; b++) r |= ((x >> b) & 1) << (K - 1 - b);
    return r;
}

__device__ __forceinline__ float2 cmul(float2 a, float2 w) {
    return make_float2(a.x * w.x - a.y * w.y, a.x * w.y + a.y * w.x);
}

__device__ __forceinline__ void pf_l2(const float2* p) {
    asm volatile("prefetch.global.L2 [%0];" :: "l"(p));
}

// Full-prefetch in-register DIF butterfly network, K stages at offset S0.
template <int S0, int K>
__device__ __forceinline__ void bnet_pf(float2* a, unsigned jj,
                                        const float2* __restrict__ W) {
    float2 tw[(1 << K) - 1];
#pragma unroll
    for (int u = 0; u < K; u++) {
#pragma unroll
        for (int c = 0; c < (1 << u); c++) {
            unsigned idx = (jj << (22 - S0 - u)) + ((unsigned)c << (22 - u));
            tw[(1 << u) - 1 + c] = __ldg(&W[idx]);
        }
    }
#pragma unroll
    for (int u = 0; u < K; u++) {
        const int half = 1 << (K - 1 - u);
#pragma unroll
        for (int t = 0; t < (1 << K) / 2; t++) {
            const int q1 = ((t & ~(half - 1)) << 1) | (t & (half - 1));
            const int q2 = q1 + half;
            const int c = brev_c(q1, K) & ((1 << u) - 1);
            float2 w = tw[(1 << u) - 1 + c];
            float2 p = cmul(a[q2], w);
            float2 tt = a[q1];
            a[q1] = make_float2(tt.x + p.x, tt.y + p.y);
            a[q2] = make_float2(tt.x - p.x, tt.y - p.y);
        }
    }
}

#define SMEM_ELEMS 16384
#define SMEM_BYTES (SMEM_ELEMS * 8)

// ============================================================================
// Kernel A: stages [0,11). R10-exact. Tile = 8 bases x 2048 q, rounds 4+4+3.
// + L2 prefetch of round-3 twiddles at kernel start (addresses known a priori).
// Output transposed: Yt[brev11(q)*4096 + base].
// ============================================================================
__device__ __forceinline__ unsigned phA(unsigned q, unsigned g) {
    unsigned l = (q << 3) | g;
    return l ^ (((l >> 6) & 1u) << 3);
}

__global__ void __launch_bounds__(512, 1)
fft_kA(const float* __restrict__ Xr, const float2* __restrict__ W,
       float2* __restrict__ Yt) {
    extern __shared__ float2 sm2[];

    const unsigned t = threadIdx.x;
    const unsigned g = t & 7u;
    const unsigned rest = t >> 3;
    const unsigned base = blockIdx.x * 8u + g;

    // early L2 prefetch: round-3 twiddles (S0=8, K=3), 7 per pass, 4 passes
#pragma unroll
    for (int pass = 0; pass < 4; pass++) {
        unsigned jj = __brev(rest + 64u * pass) >> 24;
#pragma unroll
        for (int u = 0; u < 3; u++)
#pragma unroll
            for (int c = 0; c < (1 << u); c++)
                pf_l2(&W[(jj << (14 - u)) + ((unsigned)c << (22 - u))]);
    }

    // round 1: bits q[10:7], S0=0, jj=0 (strided gmem load, imag=0)
#pragma unroll
    for (int pass = 0; pass < 2; pass++) {
        unsigned low7 = rest + 64u * pass;
        float2 a[16];
#pragma unroll
        for (int x = 0; x < 16; x++)
            a[x] = make_float2(
                __ldg(&Xr[base + ((((unsigned)x << 7) | low7) << 12)]), 0.0f);
        bnet_pf<0, 4>(a, 0u, W);
#pragma unroll
        for (int x = 0; x < 16; x++)
            sm2[phA(((unsigned)x << 7) | low7, g)] = a[x];
    }
    __syncthreads();

    // round 2: bits q[6:3], S0=4, jj = brev4(q[10:7])
#pragma unroll
    for (int pass = 0; pass < 2; pass++) {
        unsigned idx2 = rest + 64u * pass;
        unsigned lo3 = idx2 & 7u;
        unsigned H = idx2 >> 3;
        unsigned jj = __brev(H) >> 28;
        float2 a[16];
#pragma unroll
        for (int x = 0; x < 16; x++)
            a[x] = sm2[phA((H << 7) | ((unsigned)x << 3) | lo3, g)];
        bnet_pf<4, 4>(a, jj, W);
#pragma unroll
        for (int x = 0; x < 16; x++)
            sm2[phA((H << 7) | ((unsigned)x << 3) | lo3, g)] = a[x];
    }
    __syncthreads();

    // round 3: bits q[2:0], S0=8, K=3, jj = brev8(q[10:3]); write transposed
#pragma unroll
    for (int pass = 0; pass < 4; pass++) {
        unsigned B = rest + 64u * pass;
        unsigned jj = __brev(B) >> 24;
        float2 a[8];
#pragma unroll
        for (int x = 0; x < 8; x++)
            a[x] = sm2[phA((B << 3) | (unsigned)x, g)];
        bnet_pf<8, 3>(a, jj, W);
#pragma unroll
        for (int x = 0; x < 8; x++) {
            unsigned C = ((unsigned)brev_c(x, 3) << 8) | jj;
            Yt[C * 4096u + base] = a[x];
        }
    }
}

// ============================================================================
// Kernel B: stages [11,23). R10-exact. Tile = 4 j x 4096 q, rounds 4+4+4.
// + L2 prefetch of round-2 and round-3 twiddle sets at kernel start.
// Output: Out[(brev12(q) << 11) + j], streaming stores.
// ============================================================================
__device__ __forceinline__ unsigned phB(unsigned q, unsigned js) {
    unsigned l = (q << 2) | js;
    return l ^ ((l >> 4) & 3u) ^ (((l >> 6) & 3u) << 2);
}

__global__ void __launch_bounds__(512, 1)
fft_kB(const float2* __restrict__ In, const float2* __restrict__ W,
       float2* __restrict__ Out) {
    extern __shared__ float2 sm2[];

    const unsigned t = threadIdx.x;
    const unsigned j0 = blockIdx.x * 4u;
    const unsigned jg = t & 3u;
    const unsigned rest = t >> 2;              // 0..127
    const unsigned jB = j0 + jg;

    // early L2 prefetch: R2 (S0=15) and R3 (S0=19) twiddles, both passes
#pragma unroll
    for (int pass = 0; pass < 2; pass++) {
        unsigned H = (rest + 128u * pass) >> 4;
        unsigned jj2 = jB + ((__brev(H) >> 28) << 11);
#pragma unroll
        for (int u = 0; u < 4; u++)
#pragma unroll
            for (int c = 0; c < (1 << u); c++)
                pf_l2(&W[(jj2 << (7 - u)) + ((unsigned)c << (22 - u))]);

        unsigned B = rest + 128u * pass;
        unsigned jj3 = jB + ((__brev(B) >> 24) << 11);
#pragma unroll
        for (int u = 0; u < 4; u++)
#pragma unroll
            for (int c = 0; c < (1 << u); c++)
                pf_l2(&W[(jj3 << (3 - u)) + ((unsigned)c << (22 - u))]);
    }

    // round 1: bits q[11:8], S0=11. jg1 = t>>7 (warp-uniform jB),
    // 32 consecutive q per warp => coalesced LDG + uniform twiddles.
    {
        const unsigned jg1 = t >> 7;
        const unsigned lowt = t & 127u;
        const unsigned jB1 = j0 + jg1;
#pragma unroll
        for (int pass = 0; pass < 2; pass++) {
            unsigned low8 = lowt + 128u * pass;
            float2 a[16];
#pragma unroll
            for (int x = 0; x < 16; x++)
                a[x] = __ldcs(&In[jB1 * 4096u + (((unsigned)x << 8) | low8)]);
            bnet_pf<11, 4>(a, jB1, W);
#pragma unroll
            for (int x = 0; x < 16; x++) {
                unsigned q = ((unsigned)x << 8) | low8;
                sm2[phB(q, jg1)] = a[x];
            }
        }
    }
    __syncthreads();

    // round 2: bits q[7:4], S0=15, jj = jB + brev4(q[11:8])<<11
#pragma unroll
    for (int pass = 0; pass < 2; pass++) {
        unsigned idx2 = rest + 128u * pass;
        unsigned lo4 = idx2 & 15u;
        unsigned H = idx2 >> 4;
        unsigned jj = jB + ((__brev(H) >> 28) << 11);
        float2 a[16];
#pragma unroll
        for (int x = 0; x < 16; x++)
            a[x] = sm2[phB((H << 8) | ((unsigned)x << 4) | lo4, jg)];
        bnet_pf<15, 4>(a, jj, W);
#pragma unroll
        for (int x = 0; x < 16; x++)
            sm2[phB((H << 8) | ((unsigned)x << 4) | lo4, jg)] = a[x];
    }
    __syncthreads();

    // round 3: bits q[3:0], S0=19, jj = jB + brev8(q[11:4])<<11; write out
#pragma unroll
    for (int pass = 0; pass < 2; pass++) {
        unsigned B = rest + 128u * pass;
        unsigned Brev = __brev(B) >> 24;
        unsigned jj = jB + (Brev << 11);
        float2 a[16];
#pragma unroll
        for (int x = 0; x < 16; x++)
            a[x] = sm2[phB((B << 4) | (unsigned)x, jg)];
        bnet_pf<19, 4>(a, jj, W);
#pragma unroll
        for (int x = 0; x < 16; x++) {
            unsigned C = ((unsigned)brev_c(x, 4) << 8) | Brev;
            __stcs(&Out[(C << 11) + jB], a[x]);
        }
    }
}

// ---------------------------------------------------------------------------
extern "C" void kernel_launch(void* const* d_in, const int* in_sizes, int n_in,
                              void* d_out, int out_size) {
    const float* inp = (const float*)d_in[0];
    const float2* w = (const float2*)d_in[1];
    float2* out = (float2*)d_out;

    float2* scr = nullptr;
    cudaGetSymbolAddress((void**)&scr, g_scratch);

    cudaFuncSetAttribute(fft_kA, cudaFuncAttributeMaxDynamicSharedMemorySize,
                         SMEM_BYTES);
    cudaFuncSetAttribute(fft_kB, cudaFuncAttributeMaxDynamicSharedMemorySize,
                         SMEM_BYTES);

    fft_kA<<<512, 512, SMEM_BYTES>>>(inp, w, scr);   // stages 0..10
    fft_kB<<<512, 512, SMEM_BYTES>>>(scr, w, out);   // stages 11..22
}

// round 16
// speedup vs baseline: 1.3321x; 1.3321x over previous
#include <cuda_runtime.h>
#include <cuda_bf16.h>
#include <cstdint>

#define N_TOTAL 8388608   // 2^23

__device__ float2 g_scratch[N_TOTAL];   // transposed intermediate

__host__ __device__ __forceinline__ constexpr int brev_c(int x, int K) {
    int r = 0;
    for (int b = 0; b < K; b++) r |= ((x >> b) & 1) << (K - 1 - b);
    return r;
}

__device__ __forceinline__ float2 cmul(float2 a, float2 w) {
    return make_float2(a.x * w.x - a.y * w.y, a.x * w.y + a.y * w.x);
}

// load the full twiddle set for a K-stage network at offset S0
template <int S0, int K>
__device__ __forceinline__ void tw_load(float2* tw, unsigned jj,
                                        const float2* __restrict__ W) {
#pragma unroll
    for (int u = 0; u < K; u++)
#pragma unroll
        for (int c = 0; c < (1 << u); c++)
            tw[(1 << u) - 1 + c] =
                __ldg(&W[(jj << (22 - S0 - u)) + ((unsigned)c << (22 - u))]);
}

// run a K-stage in-register DIF network with preloaded twiddles
template <int K>
__device__ __forceinline__ void bnet_run(float2* a, const float2* tw) {
#pragma unroll
    for (int u = 0; u < K; u++) {
        const int half = 1 << (K - 1 - u);
#pragma unroll
        for (int t = 0; t < (1 << K) / 2; t++) {
            const int q1 = ((t & ~(half - 1)) << 1) | (t & (half - 1));
            const int q2 = q1 + half;
            const int c = brev_c(q1, K) & ((1 << u) - 1);
            float2 w = tw[(1 << u) - 1 + c];
            float2 p = cmul(a[q2], w);
            float2 tt = a[q1];
            a[q1] = make_float2(tt.x + p.x, tt.y + p.y);
            a[q2] = make_float2(tt.x - p.x, tt.y - p.y);
        }
    }
}

// combined load+run (used where hoisting isn't needed)
template <int S0, int K>
__device__ __forceinline__ void bnet_pf(float2* a, unsigned jj,
                                        const float2* __restrict__ W) {
    float2 tw[(1 << K) - 1];
    tw_load<S0, K>(tw, jj, W);
    bnet_run<K>(a, tw);
}

#define SMEM_ELEMS 16384
#define SMEM_BYTES (SMEM_ELEMS * 8)

// ============================================================================
// Kernel A: stages [0,11). R10 structure. Tile = 8 bases x 2048 q, 4+4+3.
// R3: twiddles for pass-pairs hoisted (14 f2 in flight before compute).
// Output transposed: Yt[brev11(q)*4096 + base].
// ============================================================================
__device__ __forceinline__ unsigned phA(unsigned q, unsigned g) {
    unsigned l = (q << 3) | g;
    return l ^ (((l >> 6) & 1u) << 3);
}

__global__ void __launch_bounds__(512, 1)
fft_kA(const float* __restrict__ Xr, const float2* __restrict__ W,
       float2* __restrict__ Yt) {
    extern __shared__ float2 sm2[];

    const unsigned t = threadIdx.x;
    const unsigned g = t & 7u;
    const unsigned rest = t >> 3;
    const unsigned base = blockIdx.x * 8u + g;

    // round 1: bits q[10:7], S0=0, jj=0 (strided gmem load, imag=0)
#pragma unroll
    for (int pass = 0; pass < 2; pass++) {
        unsigned low7 = rest + 64u * pass;
        float2 a[16];
#pragma unroll
        for (int x = 0; x < 16; x++)
            a[x] = make_float2(
                __ldg(&Xr[base + ((((unsigned)x << 7) | low7) << 12)]), 0.0f);
        bnet_pf<0, 4>(a, 0u, W);
#pragma unroll
        for (int x = 0; x < 16; x++)
            sm2[phA(((unsigned)x << 7) | low7, g)] = a[x];
    }
    __syncthreads();

    // round 2: bits q[6:3], S0=4, jj = brev4(q[10:7]) (warp-uniform twiddles)
#pragma unroll
    for (int pass = 0; pass < 2; pass++) {
        unsigned idx2 = rest + 64u * pass;
        unsigned lo3 = idx2 & 7u;
        unsigned H = idx2 >> 3;
        unsigned jj = __brev(H) >> 28;
        float2 a[16];
#pragma unroll
        for (int x = 0; x < 16; x++)
            a[x] = sm2[phA((H << 7) | ((unsigned)x << 3) | lo3, g)];
        bnet_pf<4, 4>(a, jj, W);
#pragma unroll
        for (int x = 0; x < 16; x++)
            sm2[phA((H << 7) | ((unsigned)x << 3) | lo3, g)] = a[x];
    }
    __syncthreads();

    // round 3: bits q[2:0], S0=8, K=3; pass-pairs with hoisted twiddles
#pragma unroll
    for (int pp = 0; pp < 2; pp++) {
        unsigned B0 = rest + 64u * (2 * pp);
        unsigned B1 = rest + 64u * (2 * pp + 1);
        unsigned jj0 = __brev(B0) >> 24;
        unsigned jj1 = __brev(B1) >> 24;
        float2 tw0[7], tw1[7];
        tw_load<8, 3>(tw0, jj0, W);
        tw_load<8, 3>(tw1, jj1, W);

        float2 a[8];
#pragma unroll
        for (int x = 0; x < 8; x++)
            a[x] = sm2[phA((B0 << 3) | (unsigned)x, g)];
        bnet_run<3>(a, tw0);
#pragma unroll
        for (int x = 0; x < 8; x++) {
            unsigned C = ((unsigned)brev_c(x, 3) << 8) | jj0;
            Yt[C * 4096u + base] = a[x];
        }
#pragma unroll
        for (int x = 0; x < 8; x++)
            a[x] = sm2[phA((B1 << 3) | (unsigned)x, g)];
        bnet_run<3>(a, tw1);
#pragma unroll
        for (int x = 0; x < 8; x++) {
            unsigned C = ((unsigned)brev_c(x, 3) << 8) | jj1;
            Yt[C * 4096u + base] = a[x];
        }
    }
}

// ============================================================================
// Kernel B: stages [11,23). R10 structure. Tile = 4 j x 4096 q, 4+4+4.
// R2/R3: both passes' twiddle sets (30 f2) hoisted before either compute.
// Output: Out[(brev12(q) << 11) + j], streaming stores.
// ============================================================================
__device__ __forceinline__ unsigned phB(unsigned q, unsigned js) {
    unsigned l = (q << 2) | js;
    return l ^ ((l >> 4) & 3u) ^ (((l >> 6) & 3u) << 2);
}

__global__ void __launch_bounds__(512, 1)
fft_kB(const float2* __restrict__ In, const float2* __restrict__ W,
       float2* __restrict__ Out) {
    extern __shared__ float2 sm2[];

    const unsigned t = threadIdx.x;
    const unsigned j0 = blockIdx.x * 4u;

    // round 1: bits q[11:8], S0=11. jg1 = t>>7 (warp-uniform jB),
    // 32 consecutive q per warp => coalesced LDG + uniform twiddles.
    {
        const unsigned jg1 = t >> 7;
        const unsigned lowt = t & 127u;
        const unsigned jB1 = j0 + jg1;
#pragma unroll
        for (int pass = 0; pass < 2; pass++) {
            unsigned low8 = lowt + 128u * pass;
            float2 a[16];
#pragma unroll
            for (int x = 0; x < 16; x++)
                a[x] = __ldcs(&In[jB1 * 4096u + (((unsigned)x << 8) | low8)]);
            bnet_pf<11, 4>(a, jB1, W);
#pragma unroll
            for (int x = 0; x < 16; x++) {
                unsigned q = ((unsigned)x << 8) | low8;
                sm2[phB(q, jg1)] = a[x];
            }
        }
    }
    __syncthreads();

    const unsigned jg = t & 3u;
    const unsigned rest = t >> 2;              // 0..127
    const unsigned jB = j0 + jg;

    // round 2: bits q[7:4], S0=15; both passes' twiddles hoisted
    {
        unsigned idx0 = rest, idx1 = rest + 128u;
        unsigned lo40 = idx0 & 15u, lo41 = idx1 & 15u;
        unsigned H0 = idx0 >> 4, H1 = idx1 >> 4;
        unsigned jj0 = jB + ((__brev(H0) >> 28) << 11);
        unsigned jj1 = jB + ((__brev(H1) >> 28) << 11);
        float2 tw0[15], tw1[15];
        tw_load<15, 4>(tw0, jj0, W);
        tw_load<15, 4>(tw1, jj1, W);

        float2 a[16];
#pragma unroll
        for (int x = 0; x < 16; x++)
            a[x] = sm2[phB((H0 << 8) | ((unsigned)x << 4) | lo40, jg)];
        bnet_run<4>(a, tw0);
#pragma unroll
        for (int x = 0; x < 16; x++)
            sm2[phB((H0 << 8) | ((unsigned)x << 4) | lo40, jg)] = a[x];

#pragma unroll
        for (int x = 0; x < 16; x++)
            a[x] = sm2[phB((H1 << 8) | ((unsigned)x << 4) | lo41, jg)];
        bnet_run<4>(a, tw1);
#pragma unroll
        for (int x = 0; x < 16; x++)
            sm2[phB((H1 << 8) | ((unsigned)x << 4) | lo41, jg)] = a[x];
    }
    __syncthreads();

    // round 3: bits q[3:0], S0=19; both passes' twiddles hoisted
    {
        unsigned B0 = rest, B1 = rest + 128u;
        unsigned Br0 = __brev(B0) >> 24, Br1 = __brev(B1) >> 24;
        unsigned jj0 = jB + (Br0 << 11);
        unsigned jj1 = jB + (Br1 << 11);
        float2 tw0[15], tw1[15];
        tw_load<19, 4>(tw0, jj0, W);
        tw_load<19, 4>(tw1, jj1, W);

        float2 a[16];
#pragma unroll
        for (int x = 0; x < 16; x++)
            a[x] = sm2[phB((B0 << 4) | (unsigned)x, jg)];
        bnet_run<4>(a, tw0);
#pragma unroll
        for (int x = 0; x < 16; x++) {
            unsigned C = ((unsigned)brev_c(x, 4) << 8) | Br0;
            __stcs(&Out[(C << 11) + jB], a[x]);
        }

#pragma unroll
        for (int x = 0; x < 16; x++)
            a[x] = sm2[phB((B1 << 4) | (unsigned)x, jg)];
        bnet_run<4>(a, tw1);
#pragma unroll
        for (int x = 0; x < 16; x++) {
            unsigned C = ((unsigned)brev_c(x, 4) << 8) | Br1;
            __stcs(&Out[(C << 11) + jB], a[x]);
        }
    }
}

// ---------------------------------------------------------------------------
extern "C" void kernel_launch(void* const* d_in, const int* in_sizes, int n_in,
                              void* d_out, int out_size) {
    const float* inp = (const float*)d_in[0];
    const float2* w = (const float2*)d_in[1];
    float2* out = (float2*)d_out;

    float2* scr = nullptr;
    cudaGetSymbolAddress((void**)&scr, g_scratch);

    cudaFuncSetAttribute(fft_kA, cudaFuncAttributeMaxDynamicSharedMemorySize,
                         SMEM_BYTES);
    cudaFuncSetAttribute(fft_kB, cudaFuncAttributeMaxDynamicSharedMemorySize,
                         SMEM_BYTES);

    fft_kA<<<512, 512, SMEM_BYTES>>>(inp, w, scr);   // stages 0..10
    fft_kB<<<512, 512, SMEM_BYTES>>>(scr, w, out);   // stages 11..22
}